// round 1
// baseline (speedup 1.0000x reference)
#include <cuda_runtime.h>

#define TT 512
#define BB 128
#define EE 128
#define SS 1024
#define LOG2T 10

// Scratch (device globals; no allocation allowed in kernel_launch)
__device__ float g_h[BB][TT + 1];      // g_h[b][0] = 0 (= h_{-1}), g_h[b][t+1] = h_t = UU_t - PP_t
__device__ float g_e[BB][TT];          // e[tau] = h_{tau-1} - d1_tau
__device__ float g_gtop[BB][TT];       // G_t(t) = h_t - u_t
__device__ float g_st[BB][LOG2T][TT];  // sparse table (range max) over h_t
__device__ float g_m[TT][SS];          // m[t][s] = max_b (u - used)
__device__ float g_w[BB][TT][SS];      // weights

// ---------------------------------------------------------------------------
// K1: per-batch prefix sums (fp64) + sparse table build. One block per batch.
// ---------------------------------------------------------------------------
__global__ void k_prep(const float* __restrict__ d1,
                       const float* __restrict__ d2,
                       const float* __restrict__ uu_) {
    int b = blockIdx.x;
    int t = threadIdx.x;  // 512 threads

    float d1v = d1[t * BB + b];
    float d2v = d2[t * BB + b];
    float uv  = uu_[t * BB + b];
    double P = (double)d1v + (double)d2v;
    double U = (double)uv;

    __shared__ double sP[16], sU[16];
    int lane = t & 31, warp = t >> 5;
    double pi = P, ui = U;
    #pragma unroll
    for (int o = 1; o < 32; o <<= 1) {
        double a = __shfl_up_sync(0xffffffffu, pi, o);
        double c = __shfl_up_sync(0xffffffffu, ui, o);
        if (lane >= o) { pi += a; ui += c; }
    }
    if (lane == 31) { sP[warp] = pi; sU[warp] = ui; }
    __syncthreads();
    if (warp == 0) {
        double pw = (lane < 16) ? sP[lane] : 0.0;
        double uw = (lane < 16) ? sU[lane] : 0.0;
        #pragma unroll
        for (int o = 1; o < 16; o <<= 1) {
            double a = __shfl_up_sync(0xffffffffu, pw, o);
            double c = __shfl_up_sync(0xffffffffu, uw, o);
            if (lane >= o) { pw += a; uw += c; }
        }
        if (lane < 16) { sP[lane] = pw; sU[lane] = uw; }
    }
    __syncthreads();
    double PP = pi + (warp ? sP[warp - 1] : 0.0);  // inclusive sum of P up to t
    double UU = ui + (warp ? sU[warp - 1] : 0.0);  // inclusive sum of u up to t

    float h = (float)(UU - PP);
    g_h[b][t + 1] = h;
    if (t == 0) g_h[b][0] = 0.f;
    g_e[b][t]    = (float)((UU - U) - (PP - P) - (double)d1v);  // h_{t-1} - d1_t
    g_gtop[b][t] = (float)(UU - PP - (double)uv);               // h_t - u_t

    // Sparse table over h (clamped construction; queries always in range)
    __shared__ float buf0[TT], buf1[TT];
    buf0[t] = h;
    g_st[b][0][t] = h;
    __syncthreads();
    float* prev = buf0;
    float* cur  = buf1;
    for (int k = 1; k < LOG2T; k++) {
        int off = 1 << (k - 1);
        int j = t + off;
        if (j > TT - 1) j = TT - 1;
        float v = fmaxf(prev[t], prev[j]);
        cur[t] = v;
        g_st[b][k][t] = v;
        __syncthreads();
        float* tmp = prev; prev = cur; cur = tmp;
    }
}

// G_t(tau) = max_{j=tau..t-1} h_j (tau < t), or h_t - u_t when tau == t
__device__ __forceinline__ float range_G(int b, int tau, int t) {
    if (tau == t) return g_gtop[b][t];
    int len = t - tau;  // >= 1
    int k = 31 - __clz(len);
    const float* stb = g_st[b][k];
    return fmaxf(stb[tau], stb[t - (1 << k)]);
}

// ---------------------------------------------------------------------------
// K2: m[t][s] = max_b (u_t - used).  a(2tau) = h_t - Bv, a(2tau+1) = h_t - G.
// block = 128 threads (one per batch), handles one t x 16 taus.
// ---------------------------------------------------------------------------
__global__ void k_m(void) {
    int t = blockIdx.x;
    int tau0 = blockIdx.y * 16;
    if (tau0 > t) return;
    int b = threadIdx.x;  // 0..127
    float ht = g_h[b][t + 1];

    __shared__ float red[8];
    for (int i = 0; i < 16; i++) {
        int tau = tau0 + i;
        if (tau > t) break;  // uniform across block
        float G  = range_G(b, tau, t);
        float Bv = fmaxf(g_e[b][tau], G);
        float v1 = ht - Bv;  // a at even slot 2*tau
        float v2 = ht - G;   // a at odd  slot 2*tau+1
        #pragma unroll
        for (int o = 16; o; o >>= 1) {
            v1 = fmaxf(v1, __shfl_xor_sync(0xffffffffu, v1, o));
            v2 = fmaxf(v2, __shfl_xor_sync(0xffffffffu, v2, o));
        }
        int w = b >> 5;
        if ((b & 31) == 0) { red[w * 2] = v1; red[w * 2 + 1] = v2; }
        __syncthreads();
        if (b == 0) {
            g_m[t][2 * tau]     = fmaxf(fmaxf(red[0], red[2]), fmaxf(red[4], red[6]));
            g_m[t][2 * tau + 1] = fmaxf(fmaxf(red[1], red[3]), fmaxf(red[5], red[7]));
        }
        __syncthreads();
    }
}

// ---------------------------------------------------------------------------
// K3: materialize W[b][t][s] = min(strength, m); 0 for s > 2t+1.
// strengths(2tau) = A - Bv, strengths(2tau+1) = Bv - G.
// ---------------------------------------------------------------------------
__global__ void k_w(void) {
    int t = blockIdx.x, b = blockIdx.y;
    float* wrow = &g_w[b][t][0];
    int smax = 2 * t + 1;
    for (int s = threadIdx.x; s < SS; s += blockDim.x) {
        float w = 0.f;
        if (s <= smax) {
            int tau = s >> 1;
            float G  = range_G(b, tau, t);
            float Bv = fmaxf(g_e[b][tau], G);
            float st;
            if (s & 1) {
                st = Bv - G;
            } else {
                float A = fmaxf(g_h[b][tau], G);  // h_{tau-1}
                st = A - Bv;
            }
            w = fminf(st, g_m[t][s]);
        }
        wrow[s] = w;
    }
}

// ---------------------------------------------------------------------------
// K4: per-batch GEMM  out[t,b,:] = sum_s W[b][t][s] * V[b][s][:]
// V[b][2tau][:] = v1[tau,b,:], V[b][2tau+1][:] = v2[tau,b,:]
// 128(t) x 128(e) tile per block, K chunked by 8, 8x8 per thread.
// Triangular: block c only needs s < 256*(c+1).
// ---------------------------------------------------------------------------
__global__ void __launch_bounds__(256) k_gemm(const float* __restrict__ v1,
                                              const float* __restrict__ v2,
                                              float* __restrict__ out) {
    int c = blockIdx.x;   // 0..3
    int b = blockIdx.y;   // 0..127
    int t0 = c * 128;
    int K = 2 * (t0 + 128);  // 256*(c+1)

    __shared__ float Ws[128][8];
    __shared__ float Vs[8][128];

    int tid = threadIdx.x;
    int tx = tid & 15;   // e block (8 wide)
    int ty = tid >> 4;   // t block (8 tall)

    float acc[8][8];
    #pragma unroll
    for (int i = 0; i < 8; i++)
        #pragma unroll
        for (int j = 0; j < 8; j++) acc[i][j] = 0.f;

    int wr = tid >> 1, wc = (tid & 1) * 4;      // W tile load mapping
    int vr = tid >> 5, ve = (tid & 31) * 4;     // V tile load mapping
    const float* wbase = &g_w[b][t0][0];

    for (int s0 = 0; s0 < K; s0 += 8) {
        float4 wv = *(const float4*)(wbase + (size_t)wr * SS + s0 + wc);
        *(float4*)&Ws[wr][wc] = wv;

        int s = s0 + vr;
        int tau = s >> 1;
        const float* src = (s & 1) ? v2 : v1;
        float4 vv = *(const float4*)(src + ((size_t)tau * BB + b) * EE + ve);
        *(float4*)&Vs[vr][ve] = vv;
        __syncthreads();

        #pragma unroll
        for (int k = 0; k < 8; k++) {
            float av[8];
            #pragma unroll
            for (int i = 0; i < 8; i++) av[i] = Ws[ty * 8 + i][k];
            float4 b0 = *(const float4*)&Vs[k][tx * 8];
            float4 b1 = *(const float4*)&Vs[k][tx * 8 + 4];
            float bv[8] = {b0.x, b0.y, b0.z, b0.w, b1.x, b1.y, b1.z, b1.w};
            #pragma unroll
            for (int i = 0; i < 8; i++)
                #pragma unroll
                for (int j = 0; j < 8; j++)
                    acc[i][j] = fmaf(av[i], bv[j], acc[i][j]);
        }
        __syncthreads();
    }

    #pragma unroll
    for (int i = 0; i < 8; i++) {
        int trow = t0 + ty * 8 + i;
        float* orow = out + ((size_t)trow * BB + b) * EE + tx * 8;
        *(float4*)orow       = make_float4(acc[i][0], acc[i][1], acc[i][2], acc[i][3]);
        *(float4*)(orow + 4) = make_float4(acc[i][4], acc[i][5], acc[i][6], acc[i][7]);
    }
}

extern "C" void kernel_launch(void* const* d_in, const int* in_sizes, int n_in,
                              void* d_out, int out_size) {
    const float* v1 = (const float*)d_in[0];
    const float* v2 = (const float*)d_in[1];
    const float* d1 = (const float*)d_in[2];
    const float* d2 = (const float*)d_in[3];
    const float* u  = (const float*)d_in[4];
    float* out = (float*)d_out;

    k_prep<<<BB, TT>>>(d1, d2, u);
    k_m<<<dim3(TT, 32), BB>>>();
    k_w<<<dim3(TT, BB), 256>>>();
    k_gemm<<<dim3(4, BB), 256>>>(v1, v2, out);
}